// round 1
// baseline (speedup 1.0000x reference)
#include <cuda_runtime.h>

#define BB   8
#define TT   48
#define CC   684
#define HH   16
#define WWD  64
#define HWN  1024
#define HIDN 256
#define AA   512
#define VV   111
#define LOCN 432

// ---------------- device scratch (static; no allocation) ----------------
__device__ float g_mask2[BB*HWN];
__device__ float g_msum[BB];
__device__ float g_hidden[BB*HIDN];
__device__ float g_locw[BB*HIDN];
__device__ float g_query[BB*AA];
__device__ float g_et[BB*HIDN];
__device__ float g_alpha_sum[BB*HWN];
__device__ float g_alpham[BB*HWN];
__device__ float g_energy[BB*HWN];
__device__ float g_ctx[BB*CC];
__device__ float g_M[121*AA];          // fused K_cov * W_cov
__device__ float g_KfT[CC*AA];         // K_feat transposed [c][a]
__device__ float g_WihT[HIDN*3*HIDN];  // [i][gate_j]
__device__ float g_WhhT[HIDN*3*HIDN];
__device__ float g_trans[(size_t)BB*HWN*AA]; // 16.7 MB, L2-resident

__device__ __forceinline__ float wred(float v){
    #pragma unroll
    for (int o=16;o;o>>=1) v += __shfl_xor_sync(0xFFFFFFFFu, v, o);
    return v;
}

// ---------------- setup kernels ----------------

// transpose W_ih, W_hh (768x256 -> [i][j]) and K_feat (512x684 -> [c][a])
__global__ void k_prep_w(const float* __restrict__ W_ih,
                         const float* __restrict__ W_hh,
                         const float* __restrict__ K_feat){
    int i = blockIdx.x*256 + threadIdx.x;
    if (i < 768*256){
        int r = i/256, c = i%256;
        g_WihT[c*768 + r] = W_ih[i];
        g_WhhT[c*768 + r] = W_hh[i];
    }
    if (i < 512*684){
        int a = i/684, c = i%684;
        g_KfT[c*512 + a] = K_feat[i];
    }
}

// M[p][a] = sum_c K_cov[c][p] * W_cov[c][a]
__global__ void k_covM(const float* __restrict__ K_cov,
                       const float* __restrict__ W_cov){
    int p = blockIdx.x, a = threadIdx.x;   // 121 blocks x 256 threads
    float s0 = 0.f, s1 = 0.f;
    for (int c=0;c<512;c++){
        float k = K_cov[c*121 + p];
        s0 += k * W_cov[c*512 + a];
        s1 += k * W_cov[c*512 + 256 + a];
    }
    g_M[p*AA + a]       = s0;
    g_M[p*AA + 256 + a] = s1;
}

// mask2 downsample + per-batch sum + zero alpha_sum
__global__ void k_mask(const float* __restrict__ imask){
    int b = blockIdx.x, tid = threadIdx.x;
    float s = 0.f;
    #pragma unroll
    for (int k=0;k<4;k++){
        int hw = tid + 256*k;
        int h = hw >> 6, w = hw & 63;
        float v = imask[(size_t)b*262144 + (size_t)(h*16)*1024 + w*16];
        g_mask2[b*HWN + hw] = v;
        g_alpha_sum[b*HWN + hw] = 0.f;
        s += v;
    }
    s = wred(s);
    __shared__ float sm[8];
    if ((tid & 31) == 0) sm[tid>>5] = s;
    __syncthreads();
    if (tid == 0){
        float t2 = 0.f;
        #pragma unroll
        for (int i=0;i<8;i++) t2 += sm[i];
        g_msum[b] = t2;
    }
}

// avg pooling -> hidden0, loc_w
__global__ void __launch_bounds__(256) k_init(
    const float* __restrict__ cnn, const float* __restrict__ W_init,
    const float* __restrict__ b_init, const float* __restrict__ locp,
    const float* __restrict__ W_loc, const float* __restrict__ b_loc){
    int b = blockIdx.x, tid = threadIdx.x;
    int wid = tid>>5, lane = tid&31;
    __shared__ float msh[HWN];
    __shared__ float avg[CC];
    for (int i=tid;i<HWN;i+=256) msh[i] = g_mask2[b*HWN + i];
    __syncthreads();
    float inv = 1.f / g_msum[b];
    for (int c=wid;c<CC;c+=8){
        const float* p = cnn + (size_t)(b*CC + c)*HWN;
        float s = 0.f;
        #pragma unroll
        for (int m=0;m<32;m++) s += msh[lane + 32*m] * p[lane + 32*m];
        s = wred(s);
        if (lane == 0) avg[c] = s*inv;
    }
    __syncthreads();
    int j = tid;
    float h0 = b_init[j];
    for (int c=0;c<CC;c++) h0 += avg[c]*W_init[c*HIDN + j];
    g_hidden[b*HIDN + j] = tanhf(h0);
    float lw = b_loc[j];
    for (int l=0;l<LOCN;l++) lw += locp[b*LOCN + l]*W_loc[l*HIDN + j];
    g_locw[b*HIDN + j] = lw;
}

// one-time 1x1 conv: trans[pix][a] = sum_c cnn[b][c][hw]*KfT[c][a] + b_feat[a]
__global__ void __launch_bounds__(256) k_trans(const float* __restrict__ cnn,
                                               const float* __restrict__ b_feat){
    int w0 = blockIdx.x*32, h = blockIdx.y, b = blockIdx.z;
    int tid = threadIdx.x;
    __shared__ float X[64][32];
    float acc0[32], acc1[32];
    #pragma unroll
    for (int i=0;i<32;i++){ acc0[i]=0.f; acc1[i]=0.f; }
    for (int c0=0;c0<CC;c0+=64){
        int nc = min(64, CC-c0);
        __syncthreads();
        for (int idx=tid; idx<nc*32; idx+=256){
            int cc = idx>>5, pix = idx&31;
            X[cc][pix] = cnn[(size_t)(b*CC + c0+cc)*HWN + h*WWD + w0 + pix];
        }
        __syncthreads();
        for (int cc=0; cc<nc; cc++){
            float k0 = g_KfT[(c0+cc)*AA + tid];
            float k1 = g_KfT[(c0+cc)*AA + 256 + tid];
            #pragma unroll
            for (int pix=0;pix<32;pix++){
                float x = X[cc][pix];
                acc0[pix] += x*k0;
                acc1[pix] += x*k1;
            }
        }
    }
    float bf0 = b_feat[tid], bf1 = b_feat[256+tid];
    #pragma unroll 4
    for (int pix=0;pix<32;pix++){
        size_t gp = (size_t)((b*HH + h)*WWD + w0 + pix)*AA;
        g_trans[gp + tid]       = acc0[pix] + bf0;
        g_trans[gp + 256 + tid] = acc1[pix] + bf1;
    }
}

// ---------------- per-step kernels ----------------

// GRU cell + query projection (block per batch row)
__global__ void __launch_bounds__(256) k_gru(
    const int* __restrict__ labels, const float* __restrict__ emb,
    const float* __restrict__ b_ih, const float* __restrict__ b_hh,
    const float* __restrict__ W_q,  const float* __restrict__ b_q, int t){
    int b = blockIdx.x, j = threadIdx.x;
    __shared__ float e_sh[HIDN], h_sh[HIDN], hn_sh[HIDN];
    int tok = (t == 0) ? 1 : labels[b*TT + t - 1];
    float ev = emb[tok*HIDN + j];
    float hv = g_hidden[b*HIDN + j];
    e_sh[j] = ev; h_sh[j] = hv;
    __syncthreads();
    float gir = b_ih[j], giz = b_ih[256+j], gin = b_ih[512+j];
    float ghr = b_hh[j], ghz = b_hh[256+j], ghn = b_hh[512+j];
    for (int i=0;i<HIDN;i++){
        float e = e_sh[i], hh = h_sh[i];
        const float* wi = &g_WihT[i*768];
        const float* wh = &g_WhhT[i*768];
        gir += e*wi[j];     ghr += hh*wh[j];
        giz += e*wi[256+j]; ghz += hh*wh[256+j];
        gin += e*wi[512+j]; ghn += hh*wh[512+j];
    }
    float r  = 1.f/(1.f + expf(-(gir + ghr)));
    float z  = 1.f/(1.f + expf(-(giz + ghz)));
    float n  = tanhf(gin + r*ghn);
    float hn = (1.f - z)*n + z*hv;
    g_hidden[b*HIDN + j] = hn;
    g_et[b*HIDN + j] = ev;
    hn_sh[j] = hn;
    __syncthreads();
    float q0 = b_q[j], q1 = b_q[256+j];
    for (int i=0;i<HIDN;i++){
        float hni = hn_sh[i];
        q0 += hni*W_q[i*AA + j];
        q1 += hni*W_q[i*AA + 256 + j];
    }
    g_query[b*AA + j]       = q0;
    g_query[b*AA + 256 + j] = q1;
}

// fused coverage-conv + attention energy (the hot kernel)
__global__ void __launch_bounds__(256) k_energy(const float* __restrict__ w_alpha,
                                                const float* __restrict__ b_alpha){
    int w0 = blockIdx.x*32, h = blockIdx.y, b = blockIdx.z;
    int tid = threadIdx.x;
    __shared__ float nb[11][42];
    __shared__ float part[32][256];
    for (int idx=tid; idx<11*42; idx+=256){
        int r = idx/42, cc = idx%42;
        int gh = h - 5 + r, gw = w0 - 5 + cc;
        float v = 0.f;
        if (gh >= 0 && gh < HH && gw >= 0 && gw < WWD)
            v = g_alpha_sum[b*HWN + gh*WWD + gw];
        nb[r][cc] = v;
    }
    __syncthreads();
    float acc0[32], acc1[32];
    #pragma unroll
    for (int i=0;i<32;i++){ acc0[i]=0.f; acc1[i]=0.f; }
    for (int py=0; py<11; py++){
        for (int px=0; px<11; px++){
            int p = py*11 + px;
            float m0 = g_M[p*AA + tid];
            float m1 = g_M[p*AA + 256 + tid];
            const float* row = &nb[py][px];
            #pragma unroll
            for (int pix=0;pix<32;pix++){
                float v = row[pix];
                acc0[pix] += v*m0;
                acc1[pix] += v*m1;
            }
        }
    }
    float q0 = g_query[b*AA + tid], q1 = g_query[b*AA + 256 + tid];
    float wa0 = w_alpha[tid], wa1 = w_alpha[256 + tid];
    #pragma unroll 4
    for (int pix=0;pix<32;pix++){
        size_t gp = (size_t)((b*HH + h)*WWD + w0 + pix)*AA;
        float s0 = tanhf(q0 + g_trans[gp + tid]       + acc0[pix]);
        float s1 = tanhf(q1 + g_trans[gp + 256 + tid] + acc1[pix]);
        part[pix][tid] = wa0*s0 + wa1*s1;
    }
    __syncthreads();
    int wid = tid>>5, lane = tid&31;
    float ba = b_alpha[0];
    #pragma unroll
    for (int k=0;k<4;k++){
        int pix = wid*4 + k;
        float s = 0.f;
        #pragma unroll
        for (int m=0;m<8;m++) s += part[pix][lane + 32*m];
        s = wred(s);
        if (lane == 0) g_energy[b*HWN + h*WWD + w0 + pix] = s + ba;
    }
}

// global max, exp, per-batch softmax, alpha_sum update, alpha outputs
__global__ void __launch_bounds__(1024) k_softmax(float* __restrict__ alphas_out, int t){
    int tid = threadIdx.x;
    int base = tid*8;
    int b = tid >> 7;
    float e[8];
    float mx = -1e30f;
    #pragma unroll
    for (int k=0;k<8;k++){ e[k] = g_energy[base + k]; mx = fmaxf(mx, e[k]); }
    #pragma unroll
    for (int o=16;o;o>>=1) mx = fmaxf(mx, __shfl_xor_sync(0xFFFFFFFFu, mx, o));
    __shared__ float sm[32];
    __shared__ float ssum[8];
    if ((tid & 31) == 0) sm[tid>>5] = mx;
    if (tid < 8) ssum[tid] = 0.f;
    __syncthreads();
    if (tid < 32){
        float v = sm[tid];
        #pragma unroll
        for (int o=16;o;o>>=1) v = fmaxf(v, __shfl_xor_sync(0xFFFFFFFFu, v, o));
        if (tid == 0) sm[0] = v;
    }
    __syncthreads();
    mx = sm[0];
    float loc = 0.f;
    #pragma unroll
    for (int k=0;k<8;k++){
        e[k] = expf(e[k] - mx) * g_mask2[base + k];
        loc += e[k];
    }
    loc = wred(loc);
    if ((tid & 31) == 0) atomicAdd(&ssum[b], loc);
    __syncthreads();
    float inv = 1.f/(ssum[b] + 1e-10f);
    #pragma unroll
    for (int k=0;k<8;k++){
        float a = e[k]*inv;
        int hw = base + k - b*HWN;
        alphas_out[(size_t)(b*TT + t)*HWN + hw] = a;
        g_alpham[base + k] = (a > 0.02f) ? a : 0.f;
        g_alpha_sum[base + k] += a;
    }
}

// ctx[b][c] = sum_hw alpham*cnn
__global__ void __launch_bounds__(256) k_ctx(const float* __restrict__ cnn,
                                             float* __restrict__ ctxs_out, int t){
    int chunk = blockIdx.x, b = blockIdx.y;
    int tid = threadIdx.x, wid = tid>>5, lane = tid&31;
    __shared__ float am[HWN];
    for (int i=tid;i<HWN;i+=256) am[i] = g_alpham[b*HWN + i];
    __syncthreads();
    int cend = min(CC, (chunk+1)*171);
    for (int c = chunk*171 + wid; c < cend; c += 8){
        const float* p = cnn + (size_t)(b*CC + c)*HWN;
        float s = 0.f;
        #pragma unroll
        for (int m=0;m<32;m++) s += am[lane + 32*m]*p[lane + 32*m];
        s = wred(s);
        if (lane == 0){
            g_ctx[b*CC + c] = s;
            ctxs_out[(size_t)t*BB*CC + b*CC + c] = s;
        }
    }
}

// out_state (maxout with loc_w) + vocab projection
__global__ void __launch_bounds__(256) k_out(
    const float* __restrict__ W_state, const float* __restrict__ b_state,
    const float* __restrict__ W_emb,   const float* __restrict__ b_emb,
    const float* __restrict__ W_ctx,   const float* __restrict__ b_ctx,
    const float* __restrict__ W_out,   const float* __restrict__ b_out,
    float* __restrict__ probs_out, float* __restrict__ outs_out, int t){
    int b = blockIdx.x, j = threadIdx.x;
    __shared__ float h_sh[HIDN], e_sh[HIDN], c_sh[CC], s_sh[HIDN];
    h_sh[j] = g_hidden[b*HIDN + j];
    e_sh[j] = g_et[b*HIDN + j];
    for (int i=j;i<CC;i+=256) c_sh[i] = g_ctx[b*CC + i];
    __syncthreads();
    float s = b_state[j] + b_emb[j] + b_ctx[j];
    for (int i=0;i<HIDN;i++)
        s += h_sh[i]*W_state[i*HIDN + j] + e_sh[i]*W_emb[i*HIDN + j];
    for (int c=0;c<CC;c++)
        s += c_sh[c]*W_ctx[c*HIDN + j];
    s = fmaxf(s, g_locw[b*HIDN + j]);
    outs_out[(size_t)t*BB*HIDN + b*HIDN + j] = s;
    s_sh[j] = s;
    __syncthreads();
    if (j < VV){
        float p = b_out[j];
        for (int i=0;i<HIDN;i++) p += s_sh[i]*W_out[i*VV + j];
        probs_out[(size_t)(b*TT + t)*VV + j] = p;
    }
}

// ---------------- launch ----------------
extern "C" void kernel_launch(void* const* d_in, const int* in_sizes, int n_in,
                              void* d_out, int out_size){
    const float* cnn     = (const float*)d_in[0];
    const int*   labels  = (const int*  )d_in[1];
    const float* locp    = (const float*)d_in[2];
    const float* imask   = (const float*)d_in[3];
    /* d_in[4] labels_mask unused */
    const float* W_init  = (const float*)d_in[5];
    const float* b_init  = (const float*)d_in[6];
    const float* emb     = (const float*)d_in[7];
    const float* W_ih    = (const float*)d_in[8];
    const float* W_hh    = (const float*)d_in[9];
    const float* b_ih    = (const float*)d_in[10];
    const float* b_hh    = (const float*)d_in[11];
    const float* W_q     = (const float*)d_in[12];
    const float* b_q     = (const float*)d_in[13];
    const float* K_cov   = (const float*)d_in[14];
    const float* W_cov   = (const float*)d_in[15];
    const float* w_alpha = (const float*)d_in[16];
    const float* b_alpha = (const float*)d_in[17];
    const float* K_feat  = (const float*)d_in[18];
    const float* b_feat  = (const float*)d_in[19];
    const float* W_state = (const float*)d_in[20];
    const float* b_state = (const float*)d_in[21];
    const float* W_emb   = (const float*)d_in[22];
    const float* b_emb   = (const float*)d_in[23];
    const float* W_ctx   = (const float*)d_in[24];
    const float* b_ctx   = (const float*)d_in[25];
    const float* W_out   = (const float*)d_in[26];
    const float* b_out   = (const float*)d_in[27];
    const float* W_loc   = (const float*)d_in[28];
    const float* b_loc   = (const float*)d_in[29];

    float* out        = (float*)d_out;
    float* probs_out  = out;                                   // B*T*V
    float* alphas_out = probs_out + (size_t)BB*TT*VV;          // B*T*H*W
    float* ctxs_out   = alphas_out + (size_t)BB*TT*HWN;        // T*B*C
    float* outs_out   = ctxs_out + (size_t)TT*BB*CC;           // T*B*HID

    // setup
    k_prep_w<<<(512*684 + 255)/256, 256>>>(W_ih, W_hh, K_feat);
    k_covM<<<121, 256>>>(K_cov, W_cov);
    k_mask<<<BB, 256>>>(imask);
    k_init<<<BB, 256>>>(cnn, W_init, b_init, locp, W_loc, b_loc);
    k_trans<<<dim3(2, HH, BB), 256>>>(cnn, b_feat);

    // 48-step scan
    for (int t = 0; t < TT; t++){
        k_gru<<<BB, 256>>>(labels, emb, b_ih, b_hh, W_q, b_q, t);
        k_energy<<<dim3(2, HH, BB), 256>>>(w_alpha, b_alpha);
        k_softmax<<<1, 1024>>>(alphas_out, t);
        k_ctx<<<dim3(4, BB), 256>>>(cnn, ctxs_out, t);
        k_out<<<BB, 256>>>(W_state, b_state, W_emb, b_emb,
                           W_ctx, b_ctx, W_out, b_out,
                           probs_out, outs_out, t);
    }
    (void)in_sizes; (void)n_in; (void)out_size;
}

// round 2
// speedup vs baseline: 1.1812x; 1.1812x over previous
#include <cuda_runtime.h>

#define BB   8
#define TT   48
#define CC   684
#define HH   16
#define WWD  64
#define HWN  1024
#define HIDN 256
#define AA   512
#define VV   111
#define LOCN 432

// ---------------- device scratch (static; no allocation) ----------------
__device__ float g_mask2[BB*HWN];
__device__ float g_msum[BB];
__device__ float g_avg[BB*CC];
__device__ float g_hidden[BB*HIDN];
__device__ float g_locw[BB*HIDN];
__device__ float g_query[BB*AA];
__device__ float g_et[BB*HIDN];
__device__ float g_alpha_sum[BB*HWN];
__device__ float g_energy[BB*HWN];
__device__ float g_ctx[BB*CC];
__device__ float g_M[121*AA];          // fused K_cov * W_cov
__device__ float g_KfT[CC*AA];         // K_feat transposed [c][a]
__device__ float g_WihT[HIDN*3*HIDN];  // [i][gate_j]
__device__ float g_WhhT[HIDN*3*HIDN];
__device__ float g_trans[(size_t)BB*HWN*AA]; // 16.7 MB, L2-resident

__device__ __forceinline__ float wred(float v){
    #pragma unroll
    for (int o=16;o;o>>=1) v += __shfl_xor_sync(0xFFFFFFFFu, v, o);
    return v;
}
// fast tanh: 1 - 2/(e^{2x}+1); __expf handles overflow (inf -> 1, 0 -> -1)
__device__ __forceinline__ float ftanh(float x){
    return 1.f - __fdividef(2.f, __expf(2.f*x) + 1.f);
}
__device__ __forceinline__ float fsig(float x){
    return __fdividef(1.f, 1.f + __expf(-x));
}

// ---------------- setup kernels ----------------

__global__ void k_prep_w(const float* __restrict__ W_ih,
                         const float* __restrict__ W_hh,
                         const float* __restrict__ K_feat){
    int i = blockIdx.x*256 + threadIdx.x;
    if (i < 768*256){
        int r = i/256, c = i%256;
        g_WihT[c*768 + r] = W_ih[i];
        g_WhhT[c*768 + r] = W_hh[i];
    }
    if (i < 512*684){
        int a = i/684, c = i%684;
        g_KfT[c*512 + a] = K_feat[i];
    }
}

// M[p][a] = sum_c K_cov[c][p] * W_cov[c][a]
__global__ void k_covM(const float* __restrict__ K_cov,
                       const float* __restrict__ W_cov){
    int p = blockIdx.x, a = threadIdx.x;   // 121 blocks x 256 threads
    float s0 = 0.f, s1 = 0.f;
    #pragma unroll 4
    for (int c=0;c<512;c++){
        float k = K_cov[c*121 + p];
        s0 += k * W_cov[c*512 + a];
        s1 += k * W_cov[c*512 + 256 + a];
    }
    g_M[p*AA + a]       = s0;
    g_M[p*AA + 256 + a] = s1;
}

// mask2 downsample + per-batch sum + zero alpha_sum
__global__ void k_mask(const float* __restrict__ imask){
    int b = blockIdx.x, tid = threadIdx.x;
    float s = 0.f;
    #pragma unroll
    for (int k=0;k<4;k++){
        int hw = tid + 256*k;
        int h = hw >> 6, w = hw & 63;
        float v = imask[(size_t)b*262144 + (size_t)(h*16)*1024 + w*16];
        g_mask2[b*HWN + hw] = v;
        g_alpha_sum[b*HWN + hw] = 0.f;
        s += v;
    }
    s = wred(s);
    __shared__ float sm[8];
    if ((tid & 31) == 0) sm[tid>>5] = s;
    __syncthreads();
    if (tid == 0){
        float t2 = 0.f;
        #pragma unroll
        for (int i=0;i<8;i++) t2 += sm[i];
        g_msum[b] = t2;
    }
}

// masked average pooling, parallel over (channel-slice, batch)
__global__ void __launch_bounds__(256) k_avg(const float* __restrict__ cnn){
    int slice = blockIdx.x, b = blockIdx.y;
    int tid = threadIdx.x, wid = tid>>5, lane = tid&31;
    __shared__ float msh[HWN];
    for (int i=tid;i<HWN;i+=256) msh[i] = g_mask2[b*HWN + i];
    __syncthreads();
    float inv = __fdividef(1.f, g_msum[b]);
    int c0 = slice*86, cend = min(CC, c0+86);
    for (int c=c0+wid;c<cend;c+=8){
        const float* p = cnn + (size_t)(b*CC + c)*HWN;
        float s = 0.f;
        #pragma unroll
        for (int m=0;m<32;m++) s += msh[lane + 32*m] * p[lane + 32*m];
        s = wred(s);
        if (lane == 0) g_avg[b*CC + c] = s*inv;
    }
}

// hidden0 = tanh(avg @ W_init), loc_w = locp @ W_loc
__global__ void __launch_bounds__(256) k_init2(
    const float* __restrict__ W_init, const float* __restrict__ b_init,
    const float* __restrict__ locp,   const float* __restrict__ W_loc,
    const float* __restrict__ b_loc){
    int b = blockIdx.x, j = threadIdx.x;
    __shared__ float avg[CC];
    __shared__ float lp[LOCN];
    for (int i=j;i<CC;i+=256) avg[i] = g_avg[b*CC + i];
    for (int i=j;i<LOCN;i+=256) lp[i] = locp[b*LOCN + i];
    __syncthreads();
    float h0 = b_init[j];
    #pragma unroll 4
    for (int c=0;c<CC;c++) h0 += avg[c]*W_init[c*HIDN + j];
    g_hidden[b*HIDN + j] = ftanh(h0);
    float lw = b_loc[j];
    #pragma unroll 4
    for (int l=0;l<LOCN;l++) lw += lp[l]*W_loc[l*HIDN + j];
    g_locw[b*HIDN + j] = lw;
}

// one-time 1x1 conv: trans[pix][a] = sum_c cnn[b][c][hw]*KfT[c][a] + b_feat[a]
__global__ void __launch_bounds__(256) k_trans(const float* __restrict__ cnn,
                                               const float* __restrict__ b_feat){
    int w0 = blockIdx.x*32, h = blockIdx.y, b = blockIdx.z;
    int tid = threadIdx.x;
    __shared__ float X[64][32];
    float acc0[32], acc1[32];
    #pragma unroll
    for (int i=0;i<32;i++){ acc0[i]=0.f; acc1[i]=0.f; }
    for (int c0=0;c0<CC;c0+=64){
        int nc = min(64, CC-c0);
        __syncthreads();
        for (int idx=tid; idx<nc*32; idx+=256){
            int cc = idx>>5, pix = idx&31;
            X[cc][pix] = cnn[(size_t)(b*CC + c0+cc)*HWN + h*WWD + w0 + pix];
        }
        __syncthreads();
        #pragma unroll 2
        for (int cc=0; cc<nc; cc++){
            float k0 = g_KfT[(c0+cc)*AA + tid];
            float k1 = g_KfT[(c0+cc)*AA + 256 + tid];
            #pragma unroll
            for (int pix=0;pix<32;pix++){
                float x = X[cc][pix];
                acc0[pix] += x*k0;
                acc1[pix] += x*k1;
            }
        }
    }
    float bf0 = b_feat[tid], bf1 = b_feat[256+tid];
    #pragma unroll 4
    for (int pix=0;pix<32;pix++){
        size_t gp = (size_t)((b*HH + h)*WWD + w0 + pix)*AA;
        g_trans[gp + tid]       = acc0[pix] + bf0;
        g_trans[gp + 256 + tid] = acc1[pix] + bf1;
    }
}

// ---------------- per-step kernels ----------------

// GRU cell + query projection (block per batch row)
__global__ void __launch_bounds__(256) k_gru(
    const int* __restrict__ labels, const float* __restrict__ emb,
    const float* __restrict__ b_ih, const float* __restrict__ b_hh,
    const float* __restrict__ W_q,  const float* __restrict__ b_q, int t){
    int b = blockIdx.x, j = threadIdx.x;
    __shared__ float e_sh[HIDN], h_sh[HIDN], hn_sh[HIDN];
    int tok = (t == 0) ? 1 : labels[b*TT + t - 1];
    float ev = emb[tok*HIDN + j];
    float hv = g_hidden[b*HIDN + j];
    e_sh[j] = ev; h_sh[j] = hv;
    __syncthreads();
    float gir = b_ih[j], giz = b_ih[256+j], gin = b_ih[512+j];
    float ghr = b_hh[j], ghz = b_hh[256+j], ghn = b_hh[512+j];
    #pragma unroll 8
    for (int i=0;i<HIDN;i++){
        float e = e_sh[i], hh = h_sh[i];
        const float* wi = &g_WihT[i*768];
        const float* wh = &g_WhhT[i*768];
        gir += e*wi[j];     ghr += hh*wh[j];
        giz += e*wi[256+j]; ghz += hh*wh[256+j];
        gin += e*wi[512+j]; ghn += hh*wh[512+j];
    }
    float r  = fsig(gir + ghr);
    float z  = fsig(giz + ghz);
    float n  = ftanh(gin + r*ghn);
    float hn = (1.f - z)*n + z*hv;
    g_hidden[b*HIDN + j] = hn;
    g_et[b*HIDN + j] = ev;
    hn_sh[j] = hn;
    __syncthreads();
    float q0 = b_q[j], q1 = b_q[256+j];
    #pragma unroll 8
    for (int i=0;i<HIDN;i++){
        float hni = hn_sh[i];
        q0 += hni*W_q[i*AA + j];
        q1 += hni*W_q[i*AA + 256 + j];
    }
    g_query[b*AA + j]       = q0;
    g_query[b*AA + 256 + j] = q1;
}

// fused coverage-conv + attention energy (the hot kernel)
__global__ void __launch_bounds__(256,1) void_guard();  // (unused decl guard)
__global__ void __launch_bounds__(256,1) k_energy(const float* __restrict__ w_alpha,
                                                  const float* __restrict__ b_alpha){
    int w0 = blockIdx.x*32, h = blockIdx.y, b = blockIdx.z;
    int tid = threadIdx.x;
    __shared__ float nb[11][42];
    __shared__ float part[32][256];
    for (int idx=tid; idx<11*42; idx+=256){
        int r = idx/42, cc = idx%42;
        int gh = h - 5 + r, gw = w0 - 5 + cc;
        float v = 0.f;
        if (gh >= 0 && gh < HH && gw >= 0 && gw < WWD)
            v = g_alpha_sum[b*HWN + gh*WWD + gw];
        nb[r][cc] = v;
    }
    __syncthreads();
    float acc0[32], acc1[32];
    #pragma unroll
    for (int i=0;i<32;i++){ acc0[i]=0.f; acc1[i]=0.f; }
    #pragma unroll 1
    for (int py=0; py<11; py++){
        // batch-load this conv-row's M coefficients into registers (MLP)
        float m0v[11], m1v[11];
        #pragma unroll
        for (int px=0;px<11;px++){
            int p = py*11 + px;
            m0v[px] = g_M[p*AA + tid];
            m1v[px] = g_M[p*AA + 256 + tid];
        }
        // fully unrolled: 42 distinct LDS get CSE'd into registers
        #pragma unroll
        for (int px=0; px<11; px++){
            #pragma unroll
            for (int pix=0;pix<32;pix++){
                float v = nb[py][px+pix];
                acc0[pix] += v*m0v[px];
                acc1[pix] += v*m1v[px];
            }
        }
    }
    float q0 = g_query[b*AA + tid], q1 = g_query[b*AA + 256 + tid];
    float wa0 = w_alpha[tid], wa1 = w_alpha[256 + tid];
    #pragma unroll 4
    for (int pix=0;pix<32;pix++){
        size_t gp = (size_t)((b*HH + h)*WWD + w0 + pix)*AA;
        float s0 = ftanh(q0 + g_trans[gp + tid]       + acc0[pix]);
        float s1 = ftanh(q1 + g_trans[gp + 256 + tid] + acc1[pix]);
        part[pix][tid] = wa0*s0 + wa1*s1;
    }
    __syncthreads();
    int wid = tid>>5, lane = tid&31;
    float ba = b_alpha[0];
    #pragma unroll
    for (int k=0;k<4;k++){
        int pix = wid*4 + k;
        float s = 0.f;
        #pragma unroll
        for (int m=0;m<8;m++) s += part[pix][lane + 32*m];
        s = wred(s);
        if (lane == 0) g_energy[b*HWN + h*WWD + w0 + pix] = s + ba;
    }
}

// fused softmax + ctx: every block recomputes the (identical) softmax for its
// batch row; chunk-0 blocks commit alphas_out / alpha_sum.
__global__ void __launch_bounds__(256) k_ctx(const float* __restrict__ cnn,
                                             float* __restrict__ alphas_out,
                                             float* __restrict__ ctxs_out, int t){
    int chunk = blockIdx.x, b = blockIdx.y;
    int tid = threadIdx.x, wid = tid>>5, lane = tid&31;
    __shared__ float am[HWN];
    __shared__ float red[8];
    __shared__ float bc[2];
    // global max over ALL energies (matches reference energy.max())
    float mx = -1e30f;
    for (int i=tid;i<BB*HWN;i+=256) mx = fmaxf(mx, g_energy[i]);
    #pragma unroll
    for (int o=16;o;o>>=1) mx = fmaxf(mx, __shfl_xor_sync(0xFFFFFFFFu, mx, o));
    if (lane == 0) red[wid] = mx;
    __syncthreads();
    if (tid == 0){
        float m2 = red[0];
        #pragma unroll
        for (int i=1;i<8;i++) m2 = fmaxf(m2, red[i]);
        bc[0] = m2;
    }
    __syncthreads();
    mx = bc[0];
    // own-batch exp + sum
    float e4[4]; float loc = 0.f;
    int base = b*HWN + tid*4;
    #pragma unroll
    for (int k=0;k<4;k++){
        float e = __expf(g_energy[base+k] - mx) * g_mask2[base+k];
        e4[k] = e; loc += e;
    }
    loc = wred(loc);
    __syncthreads();          // red reuse barrier
    if (lane == 0) red[wid] = loc;
    __syncthreads();
    if (tid == 0){
        float s = 0.f;
        #pragma unroll
        for (int i=0;i<8;i++) s += red[i];
        bc[1] = __fdividef(1.f, s + 1e-10f);
    }
    __syncthreads();
    float inv = bc[1];
    #pragma unroll
    for (int k=0;k<4;k++){
        float a = e4[k]*inv;
        int hw = tid*4 + k;
        am[hw] = (a > 0.02f) ? a : 0.f;
        if (chunk == 0){
            alphas_out[(size_t)(b*TT + t)*HWN + hw] = a;
            g_alpha_sum[b*HWN + hw] += a;
        }
    }
    __syncthreads();
    // ctx dot-product over this chunk's channels
    int cend = min(CC, (chunk+1)*171);
    for (int c = chunk*171 + wid; c < cend; c += 8){
        const float* p = cnn + (size_t)(b*CC + c)*HWN;
        float s = 0.f;
        #pragma unroll
        for (int m=0;m<32;m++) s += am[lane + 32*m]*p[lane + 32*m];
        s = wred(s);
        if (lane == 0){
            g_ctx[b*CC + c] = s;
            ctxs_out[(size_t)t*BB*CC + b*CC + c] = s;
        }
    }
}

// out_state (maxout with loc_w) + vocab projection
__global__ void __launch_bounds__(256) k_out(
    const float* __restrict__ W_state, const float* __restrict__ b_state,
    const float* __restrict__ W_emb,   const float* __restrict__ b_emb,
    const float* __restrict__ W_ctx,   const float* __restrict__ b_ctx,
    const float* __restrict__ W_out,   const float* __restrict__ b_out,
    float* __restrict__ probs_out, float* __restrict__ outs_out, int t){
    int b = blockIdx.x, j = threadIdx.x;
    __shared__ float h_sh[HIDN], e_sh[HIDN], c_sh[CC], s_sh[HIDN];
    h_sh[j] = g_hidden[b*HIDN + j];
    e_sh[j] = g_et[b*HIDN + j];
    for (int i=j;i<CC;i+=256) c_sh[i] = g_ctx[b*CC + i];
    __syncthreads();
    float s = b_state[j] + b_emb[j] + b_ctx[j];
    #pragma unroll 8
    for (int i=0;i<HIDN;i++)
        s += h_sh[i]*W_state[i*HIDN + j] + e_sh[i]*W_emb[i*HIDN + j];
    #pragma unroll 8
    for (int c=0;c<CC;c++)
        s += c_sh[c]*W_ctx[c*HIDN + j];
    s = fmaxf(s, g_locw[b*HIDN + j]);
    outs_out[(size_t)t*BB*HIDN + b*HIDN + j] = s;
    s_sh[j] = s;
    __syncthreads();
    if (j < VV){
        float p = b_out[j];
        #pragma unroll 8
        for (int i=0;i<HIDN;i++) p += s_sh[i]*W_out[i*VV + j];
        probs_out[(size_t)(b*TT + t)*VV + j] = p;
    }
}

// ---------------- launch ----------------
extern "C" void kernel_launch(void* const* d_in, const int* in_sizes, int n_in,
                              void* d_out, int out_size){
    const float* cnn     = (const float*)d_in[0];
    const int*   labels  = (const int*  )d_in[1];
    const float* locp    = (const float*)d_in[2];
    const float* imask   = (const float*)d_in[3];
    /* d_in[4] labels_mask unused */
    const float* W_init  = (const float*)d_in[5];
    const float* b_init  = (const float*)d_in[6];
    const float* emb     = (const float*)d_in[7];
    const float* W_ih    = (const float*)d_in[8];
    const float* W_hh    = (const float*)d_in[9];
    const float* b_ih    = (const float*)d_in[10];
    const float* b_hh    = (const float*)d_in[11];
    const float* W_q     = (const float*)d_in[12];
    const float* b_q     = (const float*)d_in[13];
    const float* K_cov   = (const float*)d_in[14];
    const float* W_cov   = (const float*)d_in[15];
    const float* w_alpha = (const float*)d_in[16];
    const float* b_alpha = (const float*)d_in[17];
    const float* K_feat  = (const float*)d_in[18];
    const float* b_feat  = (const float*)d_in[19];
    const float* W_state = (const float*)d_in[20];
    const float* b_state = (const float*)d_in[21];
    const float* W_emb   = (const float*)d_in[22];
    const float* b_emb   = (const float*)d_in[23];
    const float* W_ctx   = (const float*)d_in[24];
    const float* b_ctx   = (const float*)d_in[25];
    const float* W_out   = (const float*)d_in[26];
    const float* b_out   = (const float*)d_in[27];
    const float* W_loc   = (const float*)d_in[28];
    const float* b_loc   = (const float*)d_in[29];

    float* out        = (float*)d_out;
    float* probs_out  = out;                                   // B*T*V
    float* alphas_out = probs_out + (size_t)BB*TT*VV;          // B*T*H*W
    float* ctxs_out   = alphas_out + (size_t)BB*TT*HWN;        // T*B*C
    float* outs_out   = ctxs_out + (size_t)TT*BB*CC;           // T*B*HID

    // setup
    k_prep_w<<<(512*684 + 255)/256, 256>>>(W_ih, W_hh, K_feat);
    k_covM<<<121, 256>>>(K_cov, W_cov);
    k_mask<<<BB, 256>>>(imask);
    k_avg<<<dim3(8, BB), 256>>>(cnn);
    k_init2<<<BB, 256>>>(W_init, b_init, locp, W_loc, b_loc);
    k_trans<<<dim3(2, HH, BB), 256>>>(cnn, b_feat);

    // 48-step scan (4 kernels/step)
    for (int t = 0; t < TT; t++){
        k_gru<<<BB, 256>>>(labels, emb, b_ih, b_hh, W_q, b_q, t);
        k_energy<<<dim3(2, HH, BB), 256>>>(w_alpha, b_alpha);
        k_ctx<<<dim3(4, BB), 256>>>(cnn, alphas_out, ctxs_out, t);
        k_out<<<BB, 256>>>(W_state, b_state, W_emb, b_emb,
                           W_ctx, b_ctx, W_out, b_out,
                           probs_out, outs_out, t);
    }
    (void)in_sizes; (void)n_in; (void)out_size;
}

// round 3
// speedup vs baseline: 1.2575x; 1.0646x over previous
#include <cuda_runtime.h>

#define BB   8
#define TT   48
#define CC   684
#define HH   16
#define WWD  64
#define HWN  1024
#define HIDN 256
#define AA   512
#define VV   111
#define LOCN 432

// ---------------- device scratch (static; no allocation) ----------------
__device__ float g_mask2[BB*HWN];
__device__ float g_msum[BB];
__device__ float g_avg[BB*CC];
__device__ float g_hidden[BB*HIDN];
__device__ float g_locw[BB*HIDN];
__device__ float g_query[BB*AA];
__device__ float g_et[BB*HIDN];
__device__ float g_alpha_sum[BB*HWN];
__device__ float g_energy[BB*HWN];
__device__ float g_ctx[BB*CC];
__device__ float g_M[121*AA];          // fused K_cov * W_cov
__device__ float g_KfT[CC*AA];         // K_feat transposed [c][a]
__device__ float g_WihT[HIDN*3*HIDN];  // [i][gate_j]
__device__ float g_WhhT[HIDN*3*HIDN];
__device__ float g_trans[(size_t)BB*HWN*AA]; // 16.7 MB, L2-resident

__device__ __forceinline__ float wred(float v){
    #pragma unroll
    for (int o=16;o;o>>=1) v += __shfl_xor_sync(0xFFFFFFFFu, v, o);
    return v;
}
// fast tanh: 1 - 2/(e^{2x}+1)
__device__ __forceinline__ float ftanh(float x){
    return 1.f - __fdividef(2.f, __expf(2.f*x) + 1.f);
}
__device__ __forceinline__ float fsig(float x){
    return __fdividef(1.f, 1.f + __expf(-x));
}

// ---------------- setup kernels ----------------

__global__ void k_prep_w(const float* __restrict__ W_ih,
                         const float* __restrict__ W_hh,
                         const float* __restrict__ K_feat){
    int i = blockIdx.x*256 + threadIdx.x;
    if (i < 768*256){
        int r = i/256, c = i%256;
        g_WihT[c*768 + r] = W_ih[i];
        g_WhhT[c*768 + r] = W_hh[i];
    }
    if (i < 512*684){
        int a = i/684, c = i%684;
        g_KfT[c*512 + a] = K_feat[i];
    }
}

// M[p][a] = sum_c K_cov[c][p] * W_cov[c][a]
__global__ void k_covM(const float* __restrict__ K_cov,
                       const float* __restrict__ W_cov){
    int p = blockIdx.x, a = threadIdx.x;
    float s0 = 0.f, s1 = 0.f;
    #pragma unroll 4
    for (int c=0;c<512;c++){
        float k = K_cov[c*121 + p];
        s0 += k * W_cov[c*512 + a];
        s1 += k * W_cov[c*512 + 256 + a];
    }
    g_M[p*AA + a]       = s0;
    g_M[p*AA + 256 + a] = s1;
}

// mask2 downsample + per-batch sum + zero alpha_sum
__global__ void k_mask(const float* __restrict__ imask){
    int b = blockIdx.x, tid = threadIdx.x;
    float s = 0.f;
    #pragma unroll
    for (int k=0;k<4;k++){
        int hw = tid + 256*k;
        int h = hw >> 6, w = hw & 63;
        float v = imask[(size_t)b*262144 + (size_t)(h*16)*1024 + w*16];
        g_mask2[b*HWN + hw] = v;
        g_alpha_sum[b*HWN + hw] = 0.f;
        s += v;
    }
    s = wred(s);
    __shared__ float sm[8];
    if ((tid & 31) == 0) sm[tid>>5] = s;
    __syncthreads();
    if (tid == 0){
        float t2 = 0.f;
        #pragma unroll
        for (int i=0;i<8;i++) t2 += sm[i];
        g_msum[b] = t2;
    }
}

// masked average pooling
__global__ void __launch_bounds__(256) k_avg(const float* __restrict__ cnn){
    int slice = blockIdx.x, b = blockIdx.y;
    int tid = threadIdx.x, wid = tid>>5, lane = tid&31;
    __shared__ float msh[HWN];
    for (int i=tid;i<HWN;i+=256) msh[i] = g_mask2[b*HWN + i];
    __syncthreads();
    float inv = __fdividef(1.f, g_msum[b]);
    int c0 = slice*86, cend = min(CC, c0+86);
    for (int c=c0+wid;c<cend;c+=8){
        const float* p = cnn + (size_t)(b*CC + c)*HWN;
        float s = 0.f;
        #pragma unroll
        for (int m=0;m<32;m++) s += msh[lane + 32*m] * p[lane + 32*m];
        s = wred(s);
        if (lane == 0) g_avg[b*CC + c] = s*inv;
    }
}

// hidden0 = tanh(avg @ W_init), loc_w = locp @ W_loc
__global__ void __launch_bounds__(256) k_init2(
    const float* __restrict__ W_init, const float* __restrict__ b_init,
    const float* __restrict__ locp,   const float* __restrict__ W_loc,
    const float* __restrict__ b_loc){
    int b = blockIdx.x, j = threadIdx.x;
    __shared__ float avg[CC];
    __shared__ float lp[LOCN];
    for (int i=j;i<CC;i+=256) avg[i] = g_avg[b*CC + i];
    for (int i=j;i<LOCN;i+=256) lp[i] = locp[b*LOCN + i];
    __syncthreads();
    float h0 = b_init[j];
    #pragma unroll 4
    for (int c=0;c<CC;c++) h0 += avg[c]*W_init[c*HIDN + j];
    g_hidden[b*HIDN + j] = ftanh(h0);
    float lw = b_loc[j];
    #pragma unroll 4
    for (int l=0;l<LOCN;l++) lw += lp[l]*W_loc[l*HIDN + j];
    g_locw[b*HIDN + j] = lw;
}

// one-time 1x1 conv (NO partial unroll on accumulator-indexed loops!)
__global__ void __launch_bounds__(256) k_trans(const float* __restrict__ cnn,
                                               const float* __restrict__ b_feat){
    int w0 = blockIdx.x*32, h = blockIdx.y, b = blockIdx.z;
    int tid = threadIdx.x;
    __shared__ float X[64][32];
    float acc0[32], acc1[32];
    #pragma unroll
    for (int i=0;i<32;i++){ acc0[i]=0.f; acc1[i]=0.f; }
    for (int c0=0;c0<CC;c0+=64){
        int nc = min(64, CC-c0);
        __syncthreads();
        for (int idx=tid; idx<nc*32; idx+=256){
            int cc = idx>>5, pix = idx&31;
            X[cc][pix] = cnn[(size_t)(b*CC + c0+cc)*HWN + h*WWD + w0 + pix];
        }
        __syncthreads();
        #pragma unroll 2
        for (int cc=0; cc<nc; cc++){
            float k0 = g_KfT[(c0+cc)*AA + tid];
            float k1 = g_KfT[(c0+cc)*AA + 256 + tid];
            #pragma unroll
            for (int pix=0;pix<32;pix++){
                float x = X[cc][pix];
                acc0[pix] += x*k0;
                acc1[pix] += x*k1;
            }
        }
    }
    float bf0 = b_feat[tid], bf1 = b_feat[256+tid];
    #pragma unroll
    for (int pix=0;pix<32;pix++){   // FULL unroll: keep acc in regs
        size_t gp = (size_t)((b*HH + h)*WWD + w0 + pix)*AA;
        g_trans[gp + tid]       = acc0[pix] + bf0;
        g_trans[gp + 256 + tid] = acc1[pix] + bf1;
    }
}

// ---------------- per-step kernels ----------------

// GRU cell + query projection (block per batch row)
__global__ void __launch_bounds__(256) k_gru(
    const int* __restrict__ labels, const float* __restrict__ emb,
    const float* __restrict__ b_ih, const float* __restrict__ b_hh,
    const float* __restrict__ W_q,  const float* __restrict__ b_q, int t){
    int b = blockIdx.x, j = threadIdx.x;
    __shared__ float e_sh[HIDN], h_sh[HIDN], hn_sh[HIDN];
    int tok = (t == 0) ? 1 : labels[b*TT + t - 1];
    float ev = emb[tok*HIDN + j];
    float hv = g_hidden[b*HIDN + j];
    e_sh[j] = ev; h_sh[j] = hv;
    __syncthreads();
    float gir = b_ih[j], giz = b_ih[256+j], gin = b_ih[512+j];
    float ghr = b_hh[j], ghz = b_hh[256+j], ghn = b_hh[512+j];
    #pragma unroll 8
    for (int i=0;i<HIDN;i++){
        float e = e_sh[i], hh = h_sh[i];
        const float* wi = &g_WihT[i*768];
        const float* wh = &g_WhhT[i*768];
        gir += e*wi[j];     ghr += hh*wh[j];
        giz += e*wi[256+j]; ghz += hh*wh[256+j];
        gin += e*wi[512+j]; ghn += hh*wh[512+j];
    }
    float r  = fsig(gir + ghr);
    float z  = fsig(giz + ghz);
    float n  = ftanh(gin + r*ghn);
    float hn = (1.f - z)*n + z*hv;
    g_hidden[b*HIDN + j] = hn;
    g_et[b*HIDN + j] = ev;
    hn_sh[j] = hn;
    __syncthreads();
    float q0 = b_q[j], q1 = b_q[256+j];
    #pragma unroll 8
    for (int i=0;i<HIDN;i++){
        float hni = hn_sh[i];
        q0 += hni*W_q[i*AA + j];
        q1 += hni*W_q[i*AA + 256 + j];
    }
    g_query[b*AA + j]       = q0;
    g_query[b*AA + 256 + j] = q1;
}

// fused coverage-conv + attention energy (the hot kernel)
__global__ void __launch_bounds__(256,1) k_energy(const float* __restrict__ w_alpha,
                                                  const float* __restrict__ b_alpha){
    int w0 = blockIdx.x*32, h = blockIdx.y, b = blockIdx.z;
    int tid = threadIdx.x;
    __shared__ float nb[11][42];
    __shared__ float part[32][256];
    for (int idx=tid; idx<11*42; idx+=256){
        int r = idx/42, cc = idx%42;
        int gh = h - 5 + r, gw = w0 - 5 + cc;
        float v = 0.f;
        if (gh >= 0 && gh < HH && gw >= 0 && gw < WWD)
            v = g_alpha_sum[b*HWN + gh*WWD + gw];
        nb[r][cc] = v;
    }
    __syncthreads();
    float acc0[32], acc1[32];
    #pragma unroll
    for (int i=0;i<32;i++){ acc0[i]=0.f; acc1[i]=0.f; }
    #pragma unroll 1
    for (int py=0; py<11; py++){
        float m0v[11], m1v[11];
        #pragma unroll
        for (int px=0;px<11;px++){
            int p = py*11 + px;
            m0v[px] = g_M[p*AA + tid];
            m1v[px] = g_M[p*AA + 256 + tid];
        }
        #pragma unroll
        for (int px=0; px<11; px++){
            #pragma unroll
            for (int pix=0;pix<32;pix++){
                float v = nb[py][px+pix];
                acc0[pix] += v*m0v[px];
                acc1[pix] += v*m1v[px];
            }
        }
    }
    float q0 = g_query[b*AA + tid], q1 = g_query[b*AA + 256 + tid];
    float wa0 = w_alpha[tid], wa1 = w_alpha[256 + tid];
    {
        size_t gbase = (size_t)((b*HH + h)*WWD + w0)*AA + tid;
        #pragma unroll
        for (int pix=0;pix<32;pix++){   // FULL unroll: acc stays in regs
            float s0 = ftanh(q0 + g_trans[gbase + (size_t)pix*AA]       + acc0[pix]);
            float s1 = ftanh(q1 + g_trans[gbase + (size_t)pix*AA + 256] + acc1[pix]);
            part[pix][tid] = wa0*s0 + wa1*s1;
        }
    }
    __syncthreads();
    int wid = tid>>5, lane = tid&31;
    float ba = b_alpha[0];
    #pragma unroll
    for (int k=0;k<4;k++){
        int pix = wid*4 + k;
        float s = 0.f;
        #pragma unroll
        for (int m=0;m<8;m++) s += part[pix][lane + 32*m];
        s = wred(s);
        if (lane == 0) g_energy[b*HWN + h*WWD + w0 + pix] = s + ba;
    }
}

// fused softmax + ctx
__global__ void __launch_bounds__(256) k_ctx(const float* __restrict__ cnn,
                                             float* __restrict__ alphas_out,
                                             float* __restrict__ ctxs_out, int t){
    int chunk = blockIdx.x, b = blockIdx.y;
    int tid = threadIdx.x, wid = tid>>5, lane = tid&31;
    __shared__ float am[HWN];
    __shared__ float red[8];
    __shared__ float bc[2];
    float mx = -1e30f;
    for (int i=tid;i<BB*HWN;i+=256) mx = fmaxf(mx, g_energy[i]);
    #pragma unroll
    for (int o=16;o;o>>=1) mx = fmaxf(mx, __shfl_xor_sync(0xFFFFFFFFu, mx, o));
    if (lane == 0) red[wid] = mx;
    __syncthreads();
    if (tid == 0){
        float m2 = red[0];
        #pragma unroll
        for (int i=1;i<8;i++) m2 = fmaxf(m2, red[i]);
        bc[0] = m2;
    }
    __syncthreads();
    mx = bc[0];
    float e4[4]; float loc = 0.f;
    int base = b*HWN + tid*4;
    #pragma unroll
    for (int k=0;k<4;k++){
        float e = __expf(g_energy[base+k] - mx) * g_mask2[base+k];
        e4[k] = e; loc += e;
    }
    loc = wred(loc);
    __syncthreads();
    if (lane == 0) red[wid] = loc;
    __syncthreads();
    if (tid == 0){
        float s = 0.f;
        #pragma unroll
        for (int i=0;i<8;i++) s += red[i];
        bc[1] = __fdividef(1.f, s + 1e-10f);
    }
    __syncthreads();
    float inv = bc[1];
    #pragma unroll
    for (int k=0;k<4;k++){
        float a = e4[k]*inv;
        int hw = tid*4 + k;
        am[hw] = (a > 0.02f) ? a : 0.f;
        if (chunk == 0){
            alphas_out[(size_t)(b*TT + t)*HWN + hw] = a;
            g_alpha_sum[b*HWN + hw] += a;
        }
    }
    __syncthreads();
    int cend = min(CC, (chunk+1)*171);
    for (int c = chunk*171 + wid; c < cend; c += 8){
        const float* p = cnn + (size_t)(b*CC + c)*HWN;
        float s = 0.f;
        #pragma unroll
        for (int m=0;m<32;m++) s += am[lane + 32*m]*p[lane + 32*m];
        s = wred(s);
        if (lane == 0){
            g_ctx[b*CC + c] = s;
            ctxs_out[(size_t)t*BB*CC + b*CC + c] = s;
        }
    }
}

// out_state (maxout with loc_w) + vocab projection
__global__ void __launch_bounds__(256) k_out(
    const float* __restrict__ W_state, const float* __restrict__ b_state,
    const float* __restrict__ W_emb,   const float* __restrict__ b_emb,
    const float* __restrict__ W_ctx,   const float* __restrict__ b_ctx,
    const float* __restrict__ W_out,   const float* __restrict__ b_out,
    float* __restrict__ probs_out, float* __restrict__ outs_out, int t){
    int b = blockIdx.x, j = threadIdx.x;
    __shared__ float h_sh[HIDN], e_sh[HIDN], c_sh[CC], s_sh[HIDN];
    h_sh[j] = g_hidden[b*HIDN + j];
    e_sh[j] = g_et[b*HIDN + j];
    for (int i=j;i<CC;i+=256) c_sh[i] = g_ctx[b*CC + i];
    __syncthreads();
    float s = b_state[j] + b_emb[j] + b_ctx[j];
    #pragma unroll 8
    for (int i=0;i<HIDN;i++)
        s += h_sh[i]*W_state[i*HIDN + j] + e_sh[i]*W_emb[i*HIDN + j];
    #pragma unroll 8
    for (int c=0;c<CC;c++)
        s += c_sh[c]*W_ctx[c*HIDN + j];
    s = fmaxf(s, g_locw[b*HIDN + j]);
    outs_out[(size_t)t*BB*HIDN + b*HIDN + j] = s;
    s_sh[j] = s;
    __syncthreads();
    if (j < VV){
        float p = b_out[j];
        #pragma unroll 8
        for (int i=0;i<HIDN;i++) p += s_sh[i]*W_out[i*VV + j];
        probs_out[(size_t)(b*TT + t)*VV + j] = p;
    }
}

// ---------------- launch ----------------
extern "C" void kernel_launch(void* const* d_in, const int* in_sizes, int n_in,
                              void* d_out, int out_size){
    const float* cnn     = (const float*)d_in[0];
    const int*   labels  = (const int*  )d_in[1];
    const float* locp    = (const float*)d_in[2];
    const float* imask   = (const float*)d_in[3];
    const float* W_init  = (const float*)d_in[5];
    const float* b_init  = (const float*)d_in[6];
    const float* emb     = (const float*)d_in[7];
    const float* W_ih    = (const float*)d_in[8];
    const float* W_hh    = (const float*)d_in[9];
    const float* b_ih    = (const float*)d_in[10];
    const float* b_hh    = (const float*)d_in[11];
    const float* W_q     = (const float*)d_in[12];
    const float* b_q     = (const float*)d_in[13];
    const float* K_cov   = (const float*)d_in[14];
    const float* W_cov   = (const float*)d_in[15];
    const float* w_alpha = (const float*)d_in[16];
    const float* b_alpha = (const float*)d_in[17];
    const float* K_feat  = (const float*)d_in[18];
    const float* b_feat  = (const float*)d_in[19];
    const float* W_state = (const float*)d_in[20];
    const float* b_state = (const float*)d_in[21];
    const float* W_emb   = (const float*)d_in[22];
    const float* b_emb   = (const float*)d_in[23];
    const float* W_ctx   = (const float*)d_in[24];
    const float* b_ctx   = (const float*)d_in[25];
    const float* W_out   = (const float*)d_in[26];
    const float* b_out   = (const float*)d_in[27];
    const float* W_loc   = (const float*)d_in[28];
    const float* b_loc   = (const float*)d_in[29];

    float* out        = (float*)d_out;
    float* probs_out  = out;
    float* alphas_out = probs_out + (size_t)BB*TT*VV;
    float* ctxs_out   = alphas_out + (size_t)BB*TT*HWN;
    float* outs_out   = ctxs_out + (size_t)TT*BB*CC;

    k_prep_w<<<(512*684 + 255)/256, 256>>>(W_ih, W_hh, K_feat);
    k_covM<<<121, 256>>>(K_cov, W_cov);
    k_mask<<<BB, 256>>>(imask);
    k_avg<<<dim3(8, BB), 256>>>(cnn);
    k_init2<<<BB, 256>>>(W_init, b_init, locp, W_loc, b_loc);
    k_trans<<<dim3(2, HH, BB), 256>>>(cnn, b_feat);

    for (int t = 0; t < TT; t++){
        k_gru<<<BB, 256>>>(labels, emb, b_ih, b_hh, W_q, b_q, t);
        k_energy<<<dim3(2, HH, BB), 256>>>(w_alpha, b_alpha);
        k_ctx<<<dim3(4, BB), 256>>>(cnn, alphas_out, ctxs_out, t);
        k_out<<<BB, 256>>>(W_state, b_state, W_emb, b_emb,
                           W_ctx, b_ctx, W_out, b_out,
                           probs_out, outs_out, t);
    }
    (void)in_sizes; (void)n_in; (void)out_size;
}

// round 5
// speedup vs baseline: 2.5325x; 2.0139x over previous
#include <cuda_runtime.h>

#define BB   8
#define TT   48
#define CC   684
#define HH   16
#define WWD  64
#define HWN  1024
#define HIDN 256
#define AA   512
#define VV   111
#define LOCN 432
#define NBLK 128

// ---------------- device scratch (static; no allocation) ----------------
__device__ unsigned g_barcnt;
__device__ float g_mask2[BB*HWN];
__device__ float g_avg[BB*CC];
__device__ float g_hidden[BB*HIDN];
__device__ float g_locw[BB*HIDN];
__device__ float g_query[BB*AA];
__device__ float g_et[BB*HIDN];
__device__ float g_alpha_sum[BB*HWN];
__device__ float g_energy[BB*HWN];
__device__ float g_ctx[BB*CC];
__device__ float g_gpart[BB*16*6*HIDN];
__device__ float g_opart[BB*4*HIDN];
__device__ float g_M[121*AA];          // fused K_cov * W_cov
__device__ float g_KfT[CC*AA];         // K_feat transposed [c][a]
__device__ float g_WihT[HIDN*768];     // [i][gate_j]
__device__ float g_WhhT[HIDN*768];
__device__ float g_trans[(size_t)BB*HWN*AA]; // 16.7 MB, L2-resident

__device__ __forceinline__ float wred(float v){
    #pragma unroll
    for (int o=16;o;o>>=1) v += __shfl_xor_sync(0xFFFFFFFFu, v, o);
    return v;
}
__device__ __forceinline__ float ftanh(float x){
    return 1.f - __fdividef(2.f, __expf(2.f*x) + 1.f);
}
__device__ __forceinline__ float fsig(float x){
    return __fdividef(1.f, 1.f + __expf(-x));
}

// grid-wide barrier (canonical ordering):
//   each thread: fence its writes -> block-sync (all fences done) ->
//   thread 0: announce arrival -> acquire-poll counter -> block-sync.
// All mutable cross-block data uses __stcg / __ldcg (L2-direct both ways).
__device__ __forceinline__ void gsync(unsigned &target){
    __threadfence();
    __syncthreads();
    target += NBLK;
    if (threadIdx.x == 0){
        atomicAdd(&g_barcnt, 1u);
        unsigned v;
        do {
            asm volatile("ld.acquire.gpu.u32 %0, [%1];" : "=r"(v) : "l"(&g_barcnt) : "memory");
        } while (v < target);
    }
    __syncthreads();
}

// ---------------- setup kernels ----------------

__global__ void k_prep_w(const float* __restrict__ W_ih,
                         const float* __restrict__ W_hh,
                         const float* __restrict__ K_feat){
    int i = blockIdx.x*256 + threadIdx.x;
    if (i < 768*256){
        int r = i/256, c = i%256;
        g_WihT[c*768 + r] = W_ih[i];
        g_WhhT[c*768 + r] = W_hh[i];
    }
    if (i < 512*684){
        int a = i/684, c = i%684;
        g_KfT[c*512 + a] = K_feat[i];
    }
}

// M[p][a] = sum_c K_cov[c][p] * W_cov[c][a]
__global__ void k_covM(const float* __restrict__ K_cov,
                       const float* __restrict__ W_cov){
    int p = blockIdx.x, a = threadIdx.x;
    float s0 = 0.f, s1 = 0.f;
    #pragma unroll 4
    for (int c=0;c<512;c++){
        float k = K_cov[c*121 + p];
        s0 += k * W_cov[c*512 + a];
        s1 += k * W_cov[c*512 + 256 + a];
    }
    g_M[p*AA + a]       = s0;
    g_M[p*AA + 256 + a] = s1;
}

// mask2 downsample + avg pooling + alpha_sum zero + barrier reset (fused)
__global__ void __launch_bounds__(256) k_avgmask(const float* __restrict__ imask,
                                                 const float* __restrict__ cnn){
    int slice = blockIdx.x, b = blockIdx.y;
    int tid = threadIdx.x, wid = tid>>5, lane = tid&31;
    __shared__ float msh[HWN];
    __shared__ float sred[8];
    float s = 0.f;
    #pragma unroll
    for (int k=0;k<4;k++){
        int hw = tid + 256*k;
        int h = hw >> 6, w = hw & 63;
        float v = imask[(size_t)b*262144 + (size_t)(h*16)*1024 + w*16];
        msh[hw] = v; s += v;
        if (slice == 0){
            g_mask2[b*HWN + hw] = v;
            g_alpha_sum[b*HWN + hw] = 0.f;
        }
    }
    if (slice == 0 && b == 0 && tid == 0) g_barcnt = 0u;
    s = wred(s);
    if (lane == 0) sred[wid] = s;
    __syncthreads();
    float tot = 0.f;
    #pragma unroll
    for (int i=0;i<8;i++) tot += sred[i];
    float inv = __fdividef(1.f, tot);
    int c0 = slice*86, cend = min(CC, c0+86);
    for (int c=c0+wid;c<cend;c+=8){
        const float* p = cnn + (size_t)(b*CC + c)*HWN;
        float acc = 0.f;
        #pragma unroll
        for (int m=0;m<32;m++) acc += msh[lane + 32*m] * p[lane + 32*m];
        acc = wred(acc);
        if (lane == 0) g_avg[b*CC + c] = acc*inv;
    }
}

// hidden0 = tanh(avg @ W_init), loc_w = locp @ W_loc
__global__ void __launch_bounds__(256) k_init2(
    const float* __restrict__ W_init, const float* __restrict__ b_init,
    const float* __restrict__ locp,   const float* __restrict__ W_loc,
    const float* __restrict__ b_loc){
    int b = blockIdx.x, j = threadIdx.x;
    __shared__ float avg[CC];
    __shared__ float lp[LOCN];
    for (int i=j;i<CC;i+=256) avg[i] = g_avg[b*CC + i];
    for (int i=j;i<LOCN;i+=256) lp[i] = locp[b*LOCN + i];
    __syncthreads();
    float h0 = b_init[j];
    #pragma unroll 4
    for (int c=0;c<CC;c++) h0 += avg[c]*W_init[c*HIDN + j];
    g_hidden[b*HIDN + j] = ftanh(h0);
    float lw = b_loc[j];
    #pragma unroll 4
    for (int l=0;l<LOCN;l++) lw += lp[l]*W_loc[l*HIDN + j];
    g_locw[b*HIDN + j] = lw;
}

// one-time 1x1 conv
__global__ void __launch_bounds__(256) k_trans(const float* __restrict__ cnn,
                                               const float* __restrict__ b_feat){
    int w0 = blockIdx.x*32, h = blockIdx.y, b = blockIdx.z;
    int tid = threadIdx.x;
    __shared__ float X[64][32];
    float acc0[32], acc1[32];
    #pragma unroll
    for (int i=0;i<32;i++){ acc0[i]=0.f; acc1[i]=0.f; }
    for (int c0=0;c0<CC;c0+=64){
        int nc = min(64, CC-c0);
        __syncthreads();
        for (int idx=tid; idx<nc*32; idx+=256){
            int cc = idx>>5, pix = idx&31;
            X[cc][pix] = cnn[(size_t)(b*CC + c0+cc)*HWN + h*WWD + w0 + pix];
        }
        __syncthreads();
        #pragma unroll 2
        for (int cc=0; cc<nc; cc++){
            float k0 = g_KfT[(c0+cc)*AA + tid];
            float k1 = g_KfT[(c0+cc)*AA + 256 + tid];
            #pragma unroll
            for (int pix=0;pix<32;pix++){
                float x = X[cc][pix];
                acc0[pix] += x*k0;
                acc1[pix] += x*k1;
            }
        }
    }
    float bf0 = b_feat[tid], bf1 = b_feat[256+tid];
    #pragma unroll
    for (int pix=0;pix<32;pix++){
        size_t gp = (size_t)((b*HH + h)*WWD + w0 + pix)*AA;
        g_trans[gp + tid]       = acc0[pix] + bf0;
        g_trans[gp + 256 + tid] = acc1[pix] + bf1;
    }
}

// ---------------- persistent scan kernel ----------------
__global__ void __launch_bounds__(256) k_persist(
    const int*   __restrict__ labels,  const float* __restrict__ emb,
    const float* __restrict__ b_ih,    const float* __restrict__ b_hh,
    const float* __restrict__ W_q,     const float* __restrict__ b_q,
    const float* __restrict__ w_alpha, const float* __restrict__ b_alpha,
    const float* __restrict__ cnn,
    const float* __restrict__ W_state, const float* __restrict__ b_state,
    const float* __restrict__ W_emb,   const float* __restrict__ b_emb,
    const float* __restrict__ W_ctx,   const float* __restrict__ b_ctx,
    const float* __restrict__ W_out,   const float* __restrict__ b_out,
    float* __restrict__ probs_out, float* __restrict__ alphas_out,
    float* __restrict__ ctxs_out,  float* __restrict__ outs_out){

    int blk = blockIdx.x;
    int tid = threadIdx.x, wid = tid>>5, lane = tid&31;
    unsigned bar = 0;

    __shared__ float s_part[32][256];   // energy partials (32 KB)
    __shared__ float s_nb[11][42];      // coverage neighborhood
    __shared__ float s_am[HWN];         // masked alpha
    __shared__ float s_vals[304];       // phase-local staging
    __shared__ float s_red[8];
    __shared__ float s_bc[2];

    for (int t = 0; t < TT; t++){
        // ---- A1: GRU gate partials (all 128 blocks; (b, part16)) ----
        {
            int b = blk >> 4, part = blk & 15;
            int tok = (t == 0) ? 1 : labels[b*TT + t - 1];
            if (tid < 16)       s_vals[tid] = emb[tok*HIDN + part*16 + tid];
            else if (tid < 32)  s_vals[tid] = __ldcg(&g_hidden[b*HIDN + part*16 + tid - 16]);
            __syncthreads();
            int j = tid;
            float p0=0.f,p1=0.f,p2=0.f,p3=0.f,p4=0.f,p5=0.f;
            #pragma unroll
            for (int ii=0; ii<16; ii++){
                int i = part*16 + ii;
                float e = s_vals[ii], hh = s_vals[16+ii];
                const float* wi = &g_WihT[i*768];
                const float* wh = &g_WhhT[i*768];
                p0 += e*wi[j];      p1 += e*wi[256+j];  p2 += e*wi[512+j];
                p3 += hh*wh[j];     p4 += hh*wh[256+j]; p5 += hh*wh[512+j];
            }
            float* gp = &g_gpart[(b*16 + part)*6*HIDN];
            __stcg(&gp[j], p0);      __stcg(&gp[256+j], p1);  __stcg(&gp[512+j], p2);
            __stcg(&gp[768+j], p3);  __stcg(&gp[1024+j], p4); __stcg(&gp[1280+j], p5);
        }
        gsync(bar);

        // ---- A2: combine gates -> hidden, e_t (8 blocks) ----
        if (blk < 8){
            int b = blk, j = tid;
            int tok = (t == 0) ? 1 : labels[b*TT + t - 1];
            float a0=b_ih[j], a1=b_ih[256+j], a2=b_ih[512+j];
            float a3=b_hh[j], a4=b_hh[256+j], a5=b_hh[512+j];
            #pragma unroll
            for (int p=0;p<16;p++){
                const float* gp = &g_gpart[(b*16 + p)*6*HIDN];
                a0 += __ldcg(&gp[j]);      a1 += __ldcg(&gp[256+j]);  a2 += __ldcg(&gp[512+j]);
                a3 += __ldcg(&gp[768+j]);  a4 += __ldcg(&gp[1024+j]); a5 += __ldcg(&gp[1280+j]);
            }
            float r = fsig(a0 + a3);
            float z = fsig(a1 + a4);
            float n = ftanh(a2 + r*a5);
            float hv = __ldcg(&g_hidden[b*HIDN + j]);
            float hn = (1.f - z)*n + z*hv;
            __stcg(&g_hidden[b*HIDN + j], hn);
            __stcg(&g_et[b*HIDN + j], emb[tok*HIDN + j]);
        }
        gsync(bar);

        // ---- A3: query = hn @ W_q (16 blocks; (b, half)) ----
        if (blk < 16){
            int b = blk >> 1, half = blk & 1;
            s_vals[tid] = __ldcg(&g_hidden[b*HIDN + tid]);
            __syncthreads();
            int j2 = half*256 + tid;
            float q = b_q[j2];
            #pragma unroll 8
            for (int i=0;i<HIDN;i++) q += s_vals[i]*W_q[i*AA + j2];
            __stcg(&g_query[b*AA + j2], q);
        }
        gsync(bar);

        // ---- B: coverage-conv + energy (all 128 blocks; (b, h); 2 tiles) ----
        {
            int b = blk >> 4, h = blk & 15;
            float q0 = __ldcg(&g_query[b*AA + tid]);
            float q1 = __ldcg(&g_query[b*AA + 256 + tid]);
            float wa0 = w_alpha[tid], wa1 = w_alpha[256 + tid];
            float ba = b_alpha[0];
            for (int tile=0; tile<2; tile++){
                int w0 = tile*32;
                __syncthreads();
                for (int idx=tid; idx<11*42; idx+=256){
                    int r = idx/42, cc = idx%42;
                    int gh = h - 5 + r, gw = w0 - 5 + cc;
                    float v = 0.f;
                    if (gh >= 0 && gh < HH && gw >= 0 && gw < WWD)
                        v = __ldcg(&g_alpha_sum[b*HWN + gh*WWD + gw]);
                    s_nb[r][cc] = v;
                }
                __syncthreads();
                float acc0[32], acc1[32];
                #pragma unroll
                for (int i=0;i<32;i++){ acc0[i]=0.f; acc1[i]=0.f; }
                #pragma unroll 1
                for (int py=0; py<11; py++){
                    float m0v[11], m1v[11];
                    #pragma unroll
                    for (int px=0;px<11;px++){
                        int p = py*11 + px;
                        m0v[px] = g_M[p*AA + tid];
                        m1v[px] = g_M[p*AA + 256 + tid];
                    }
                    #pragma unroll
                    for (int px=0; px<11; px++){
                        #pragma unroll
                        for (int pix=0;pix<32;pix++){
                            float v = s_nb[py][px+pix];
                            acc0[pix] += v*m0v[px];
                            acc1[pix] += v*m1v[px];
                        }
                    }
                }
                size_t gbase = (size_t)((b*HH + h)*WWD + w0)*AA + tid;
                #pragma unroll
                for (int pix=0;pix<32;pix++){
                    float s0 = ftanh(q0 + g_trans[gbase + (size_t)pix*AA]       + acc0[pix]);
                    float s1 = ftanh(q1 + g_trans[gbase + (size_t)pix*AA + 256] + acc1[pix]);
                    s_part[pix][tid] = wa0*s0 + wa1*s1;
                }
                __syncthreads();
                #pragma unroll
                for (int k=0;k<4;k++){
                    int pix = wid*4 + k;
                    float s = 0.f;
                    #pragma unroll
                    for (int m=0;m<8;m++) s += s_part[pix][lane + 32*m];
                    s = wred(s);
                    if (lane == 0) __stcg(&g_energy[b*HWN + h*WWD + w0 + pix], s + ba);
                }
            }
        }
        gsync(bar);

        // ---- C: softmax (redundant per block) + ctx (all 128; (b, chunk16)) ----
        {
            int b = blk >> 4, chunk = blk & 15;
            float mx = -1e30f;
            for (int i=tid;i<BB*HWN;i+=256) mx = fmaxf(mx, __ldcg(&g_energy[i]));
            #pragma unroll
            for (int o=16;o;o>>=1) mx = fmaxf(mx, __shfl_xor_sync(0xFFFFFFFFu, mx, o));
            if (lane == 0) s_red[wid] = mx;
            __syncthreads();
            if (tid == 0){
                float m2 = s_red[0];
                #pragma unroll
                for (int i=1;i<8;i++) m2 = fmaxf(m2, s_red[i]);
                s_bc[0] = m2;
            }
            __syncthreads();
            mx = s_bc[0];
            float e4[4]; float loc = 0.f;
            int base = b*HWN + tid*4;
            #pragma unroll
            for (int k=0;k<4;k++){
                float e = __expf(__ldcg(&g_energy[base+k]) - mx) * g_mask2[base+k];
                e4[k] = e; loc += e;
            }
            loc = wred(loc);
            __syncthreads();
            if (lane == 0) s_red[wid] = loc;
            __syncthreads();
            if (tid == 0){
                float s = 0.f;
                #pragma unroll
                for (int i=0;i<8;i++) s += s_red[i];
                s_bc[1] = __fdividef(1.f, s + 1e-10f);
            }
            __syncthreads();
            float inv = s_bc[1];
            #pragma unroll
            for (int k=0;k<4;k++){
                float a = e4[k]*inv;
                int hw = tid*4 + k;
                s_am[hw] = (a > 0.02f) ? a : 0.f;
                if (chunk == 0){
                    alphas_out[(size_t)(b*TT + t)*HWN + hw] = a;
                    float as = __ldcg(&g_alpha_sum[b*HWN + hw]) + a;
                    __stcg(&g_alpha_sum[b*HWN + hw], as);
                }
            }
            __syncthreads();
            int c0 = chunk*43, cend = min(CC, c0+43);
            for (int c = c0 + wid; c < cend; c += 8){
                const float* p = cnn + (size_t)(b*CC + c)*HWN;
                float s = 0.f;
                #pragma unroll
                for (int m=0;m<32;m++) s += s_am[lane + 32*m]*p[lane + 32*m];
                s = wred(s);
                if (lane == 0){
                    __stcg(&g_ctx[b*CC + c], s);
                    ctxs_out[(size_t)t*BB*CC + b*CC + c] = s;
                }
            }
        }
        gsync(bar);

        // ---- D1: out_state partials (32 blocks; (b, part4); 299 rows each) ----
        if (blk < 32){
            int b = blk >> 2, part = blk & 3;
            int lo = part*299, hi = lo + 299;
            for (int rr=tid; rr<299; rr+=256){
                int r = lo + rr;
                float v;
                if (r < 256)      v = __ldcg(&g_hidden[b*HIDN + r]);
                else if (r < 512) v = __ldcg(&g_et[b*HIDN + r - 256]);
                else              v = __ldcg(&g_ctx[b*CC + r - 512]);
                s_vals[rr] = v;
            }
            __syncthreads();
            int j = tid;
            float s = 0.f;
            int r = lo;
            int e1 = min(hi, 256);
            #pragma unroll 4
            for (; r < e1; r++) s += s_vals[r-lo]*W_state[r*HIDN + j];
            r = max(lo, 256);
            int e2 = min(hi, 512);
            #pragma unroll 4
            for (; r < e2; r++) s += s_vals[r-lo]*W_emb[(r-256)*HIDN + j];
            r = max(lo, 512);
            #pragma unroll 4
            for (; r < hi; r++) s += s_vals[r-lo]*W_ctx[(r-512)*HIDN + j];
            __stcg(&g_opart[(b*4 + part)*HIDN + j], s);
        }
        gsync(bar);

        // ---- D2: maxout + vocab projection (8 blocks) ----
        if (blk < 8){
            int b = blk, j = tid;
            float s = b_state[j] + b_emb[j] + b_ctx[j];
            #pragma unroll
            for (int p=0;p<4;p++) s += __ldcg(&g_opart[(b*4 + p)*HIDN + j]);
            s = fmaxf(s, g_locw[b*HIDN + j]);
            outs_out[(size_t)t*BB*HIDN + b*HIDN + j] = s;
            s_vals[j] = s;
            __syncthreads();
            if (j < VV){
                float pr = b_out[j];
                #pragma unroll 8
                for (int i=0;i<HIDN;i++) pr += s_vals[i]*W_out[i*VV + j];
                probs_out[(size_t)(b*TT + t)*VV + j] = pr;
            }
        }
        gsync(bar);
    }
}

// ---------------- launch ----------------
extern "C" void kernel_launch(void* const* d_in, const int* in_sizes, int n_in,
                              void* d_out, int out_size){
    const float* cnn     = (const float*)d_in[0];
    const int*   labels  = (const int*  )d_in[1];
    const float* locp    = (const float*)d_in[2];
    const float* imask   = (const float*)d_in[3];
    const float* W_init  = (const float*)d_in[5];
    const float* b_init  = (const float*)d_in[6];
    const float* emb     = (const float*)d_in[7];
    const float* W_ih    = (const float*)d_in[8];
    const float* W_hh    = (const float*)d_in[9];
    const float* b_ih    = (const float*)d_in[10];
    const float* b_hh    = (const float*)d_in[11];
    const float* W_q     = (const float*)d_in[12];
    const float* b_q     = (const float*)d_in[13];
    const float* K_cov   = (const float*)d_in[14];
    const float* W_cov   = (const float*)d_in[15];
    const float* w_alpha = (const float*)d_in[16];
    const float* b_alpha = (const float*)d_in[17];
    const float* K_feat  = (const float*)d_in[18];
    const float* b_feat  = (const float*)d_in[19];
    const float* W_state = (const float*)d_in[20];
    const float* b_state = (const float*)d_in[21];
    const float* W_emb   = (const float*)d_in[22];
    const float* b_emb   = (const float*)d_in[23];
    const float* W_ctx   = (const float*)d_in[24];
    const float* b_ctx   = (const float*)d_in[25];
    const float* W_out   = (const float*)d_in[26];
    const float* b_out   = (const float*)d_in[27];
    const float* W_loc   = (const float*)d_in[28];
    const float* b_loc   = (const float*)d_in[29];

    float* out        = (float*)d_out;
    float* probs_out  = out;                                   // B*T*V
    float* alphas_out = probs_out + (size_t)BB*TT*VV;          // B*T*H*W
    float* ctxs_out   = alphas_out + (size_t)BB*TT*HWN;        // T*B*C
    float* outs_out   = ctxs_out + (size_t)TT*BB*CC;           // T*B*HID

    k_prep_w<<<(512*684 + 255)/256, 256>>>(W_ih, W_hh, K_feat);
    k_covM<<<121, 256>>>(K_cov, W_cov);
    k_avgmask<<<dim3(8, BB), 256>>>(imask, cnn);
    k_init2<<<BB, 256>>>(W_init, b_init, locp, W_loc, b_loc);
    k_trans<<<dim3(2, HH, BB), 256>>>(cnn, b_feat);

    k_persist<<<NBLK, 256>>>(labels, emb, b_ih, b_hh, W_q, b_q,
                             w_alpha, b_alpha, cnn,
                             W_state, b_state, W_emb, b_emb,
                             W_ctx, b_ctx, W_out, b_out,
                             probs_out, alphas_out, ctxs_out, outs_out);
    (void)in_sizes; (void)n_in; (void)out_size;
}